// round 16
// baseline (speedup 1.0000x reference)
#include <cuda_runtime.h>
#include <cuda_fp16.h>
#include <math.h>
#include <stdint.h>

// ---- problem constants ----
#define D_   2048
#define H_   16
#define KVH_ 4
#define HD_  128
#define B_   2
#define T_   2048
#define BT_  (B_*T_)          // 4096
#define QCOLS_ (H_*HD_)       // 2048
#define KCOLS_ (KVH_*HD_)     // 512
#define CAP_ 50.0f
#define SCALE_ 0.08838834764831845f  // 128^-0.5

// ---- scratch (static device arrays; no allocations allowed) ----
static __device__ float  g_q[BT_*QCOLS_];      // q proj (f32, pre-norm)
static __device__ float  g_k[BT_*KCOLS_];      // k proj (f32, pre-norm)
static __device__ __half g_xh[BT_*D_];         // half copies of GEMM operands
static __device__ __half g_wqh[QCOLS_*D_];
static __device__ __half g_wkh[KCOLS_*D_];
static __device__ __half g_wvh[KCOLS_*D_];
static __device__ __half g_woh[D_*QCOLS_];
static __device__ __half g_qh[BT_*QCOLS_];     // post-norm half q
static __device__ __half g_kh[BT_*KCOLS_];     // post-norm half k
static __device__ __half g_vh[BT_*KCOLS_];     // v (half, direct from GEMM)
static __device__ __half g_oh[BT_*QCOLS_];     // attention out (half)

// ============================================================================
// helpers
// ============================================================================
__device__ __forceinline__ unsigned pack_h2(float lo, float hi) {
    unsigned u;
    asm("cvt.rn.f16x2.f32 %0, %1, %2;" : "=r"(u) : "f"(hi), "f"(lo));
    return u;
}

__device__ __forceinline__ void mma_f16(float* c, const unsigned* a, const unsigned* b) {
    asm volatile(
        "mma.sync.aligned.m16n8k16.row.col.f32.f16.f16.f32 "
        "{%0,%1,%2,%3}, {%4,%5,%6,%7}, {%8,%9}, {%0,%1,%2,%3};"
        : "+f"(c[0]), "+f"(c[1]), "+f"(c[2]), "+f"(c[3])
        : "r"(a[0]), "r"(a[1]), "r"(a[2]), "r"(a[3]), "r"(b[0]), "r"(b[1]));
}

__device__ __forceinline__ void ldsm4(unsigned& r0, unsigned& r1, unsigned& r2, unsigned& r3,
                                      unsigned addr) {
    asm volatile("ldmatrix.sync.aligned.m8n8.x4.shared.b16 {%0,%1,%2,%3}, [%4];"
        : "=r"(r0), "=r"(r1), "=r"(r2), "=r"(r3) : "r"(addr));
}

__device__ __forceinline__ void ldsm4t(unsigned& r0, unsigned& r1, unsigned& r2, unsigned& r3,
                                       unsigned addr) {
    asm volatile("ldmatrix.sync.aligned.m8n8.x4.trans.shared.b16 {%0,%1,%2,%3}, [%4];"
        : "=r"(r0), "=r"(r1), "=r"(r2), "=r"(r3) : "r"(addr));
}

__device__ __forceinline__ float tanh_fast(float x) {
    float r;
    asm("tanh.approx.f32 %0, %1;" : "=f"(r) : "f"(x));
    return r;
}

__device__ __forceinline__ void cp_async16s(unsigned saddr, const void* gsrc) {
    asm volatile("cp.async.cg.shared.global [%0], [%1], 16;" :: "r"(saddr), "l"(gsrc));
}
#define CP_COMMIT() asm volatile("cp.async.commit_group;")
#define CP_WAIT0()  asm volatile("cp.async.wait_group 0;")
#define CP_WAIT1()  asm volatile("cp.async.wait_group 1;")

// ============================================================================
// f32 -> f16 elementwise (4 floats per thread)
// ============================================================================
__global__ __launch_bounds__(256) void cvt_h(
    const float* __restrict__ in, __half* __restrict__ out, int n4)
{
    int i = blockIdx.x * 256 + threadIdx.x;
    if (i >= n4) return;
    float4 v = ((const float4*)in)[i];
    uint2 u;
    u.x = pack_h2(v.x, v.y);
    u.y = pack_h2(v.z, v.w);
    ((uint2*)out)[i] = u;
}

// ============================================================================
// fp16 GEMM v4: C[M,N] = A[M,K]*B[N,K]^T, half operands. 128(M)x256(N)x64
// tiles, 256 thr, 8 warps in 2(M)x4(N), warp tile 64x64.
// 3-stage cp.async ring with wait_group 1 (loads get ~2 compute-stages of
// slack). 144B row pad (ldmatrix phases conflict-free). 1 CTA/SM.
// ============================================================================
#define GBK 64
#define GROWB 144
#define GA_BYTES (128*GROWB)             // 18432
#define GSTG ((128+256)*GROWB)           // 55296 per stage
#define GEMMH_SMEM (3*GSTG)              // 165888

template<bool HOUT>
__global__ __launch_bounds__(256, 1) void gemm_h(
    const __half* __restrict__ A, const __half* __restrict__ Bw,
    void* __restrict__ Cv, int M, int N, int K)
{
    extern __shared__ char gsm[];
    const unsigned sb = (unsigned)__cvta_generic_to_shared(gsm);

    const int tid  = threadIdx.x;
    const int lane = tid & 31;
    const int warp = tid >> 5;
    const int gid  = lane >> 2, m4 = lane & 3;
    const int wm = (warp & 1) * 64;          // warp row offset
    const int wn = (warp >> 1) * 64;         // warp col offset
    const int rowBase = blockIdx.y * 128;
    const int colBase = blockIdx.x * 256;

    float acc[4][8][4];
#pragma unroll
    for (int mi = 0; mi < 4; mi++)
#pragma unroll
        for (int ni = 0; ni < 8; ni++)
#pragma unroll
            for (int q = 0; q < 4; q++) acc[mi][ni][q] = 0.f;

    const int nt = K / GBK;

    // stage loader: A 1024 chunks (4/thr) + B 2048 chunks (8/thr)
    auto load_stage = [&](int st, int k0) {
        unsigned base = sb + st * GSTG;
#pragma unroll
        for (int it = 0; it < 4; it++) {
            int ci = it * 256 + tid;
            int r = ci >> 3, c = ci & 7;
            cp_async16s(base + r * GROWB + c * 16,
                        A + (size_t)(rowBase + r) * K + k0 + c * 8);
        }
#pragma unroll
        for (int it = 0; it < 8; it++) {
            int ci = it * 256 + tid;
            int r = ci >> 3, c = ci & 7;
            cp_async16s(base + GA_BYTES + r * GROWB + c * 16,
                        Bw + (size_t)(colBase + r) * K + k0 + c * 8);
        }
        CP_COMMIT();
    };

    // prologue: stages 0, 1
    load_stage(0, 0);
    load_stage(1, GBK);

    // lane-invariant ldmatrix bases
    const unsigned abo = (wm + ((lane >> 3) & 1) * 8 + (lane & 7)) * GROWB + (lane >> 4) * 16;
    const unsigned bbo = GA_BYTES + (wn + (lane >> 4) * 8 + (lane & 7)) * GROWB
                       + ((lane >> 3) & 1) * 16;

    for (int t = 0; t < nt; t++) {
        const int st = t % 3;
        if (t == nt - 1) { CP_WAIT0(); } else { CP_WAIT1(); }
        __syncthreads();

        if (t + 2 < nt) load_stage((t + 2) % 3, (t + 2) * GBK);

        const unsigned ab = sb + st * GSTG + abo;
        const unsigned bb = sb + st * GSTG + bbo;
#pragma unroll
        for (int ks = 0; ks < 4; ks++) {
            unsigned a[4][4];
#pragma unroll
            for (int mi = 0; mi < 4; mi++)
                ldsm4(a[mi][0], a[mi][1], a[mi][2], a[mi][3],
                      ab + mi * (16 * GROWB) + ks * 32);
#pragma unroll
            for (int nf4 = 0; nf4 < 4; nf4++) {
                unsigned b0, b1, b2, b3;
                ldsm4(b0, b1, b2, b3, bb + nf4 * (16 * GROWB) + ks * 32);
                unsigned bl[2] = { b0, b1 };
                unsigned bh2[2] = { b2, b3 };
#pragma unroll
                for (int mi = 0; mi < 4; mi++) {
                    mma_f16(acc[mi][2*nf4],     a[mi], bl);
                    mma_f16(acc[mi][2*nf4 + 1], a[mi], bh2);
                }
            }
        }
        __syncthreads();   // protect stage st before it's reloaded as t+2 later
    }

    // ---- epilogue ----
#pragma unroll
    for (int mi = 0; mi < 4; mi++) {
        int r0 = rowBase + wm + 16 * mi + gid;
#pragma unroll
        for (int ni = 0; ni < 8; ni++) {
            int c0 = colBase + wn + ni * 8 + m4 * 2;
            if (HOUT) {
                __half* C = (__half*)Cv;
                *(unsigned*)(C + (size_t)r0       * N + c0) = pack_h2(acc[mi][ni][0], acc[mi][ni][1]);
                *(unsigned*)(C + (size_t)(r0 + 8) * N + c0) = pack_h2(acc[mi][ni][2], acc[mi][ni][3]);
            } else {
                float* C = (float*)Cv;
                *(float2*)(C + (size_t)r0       * N + c0) = make_float2(acc[mi][ni][0], acc[mi][ni][1]);
                *(float2*)(C + (size_t)(r0 + 8) * N + c0) = make_float2(acc[mi][ni][2], acc[mi][ni][3]);
            }
        }
    }
}

// ============================================================================
// RMSNorm: f32 in, half out. One warp per 128-elem row. Scale folded (q).
// ============================================================================
__global__ __launch_bounds__(256) void rmsnorm_cvt(
    const float* __restrict__ in, __half* __restrict__ out,
    const float* __restrict__ gamma, int nrows, float scale)
{
    int row  = blockIdx.x * 8 + (threadIdx.x >> 5);
    int lane = threadIdx.x & 31;
    if (row >= nrows) return;
    float4 v = ((const float4*)in)[(size_t)row * 32 + lane];
    float ss = v.x*v.x + v.y*v.y + v.z*v.z + v.w*v.w;
#pragma unroll
    for (int off = 16; off > 0; off >>= 1)
        ss += __shfl_xor_sync(0xffffffffu, ss, off);
    float r = rsqrtf(ss * (1.0f/128.0f) + 1e-6f) * scale;
    float4 g = ((const float4*)gamma)[lane];
    uint2 u;
    u.x = pack_h2(v.x * r * g.x, v.y * r * g.y);
    u.y = pack_h2(v.z * r * g.z, v.w * r * g.w);
    ((uint2*)(out + (size_t)row * 128))[lane] = u;
}

// ============================================================================
// fp16 flash attention (R15, unchanged): double-buffered K/V, ldmatrix,
// half in / half out.
// ============================================================================
#define AT_LDH 136
#define AT_ROWB (AT_LDH*2)               // 272 B per row
#define AT_TILE (64*AT_ROWB)             // 17408 B per tile
#define ATTN_SMEM (5*AT_TILE)            // 87040 B

__global__ __launch_bounds__(128) void attn_f16(
    const __half* __restrict__ Q, const __half* __restrict__ Kk,
    const __half* __restrict__ Vv, __half* __restrict__ O)
{
    extern __shared__ char smc[];
    const unsigned qs_b = (unsigned)__cvta_generic_to_shared(smc);

    const int tid  = threadIdx.x;
    const int lane = tid & 31;
    const int warp = tid >> 5;
    const int gid  = lane >> 2;
    const int m4   = lane & 3;

    const int bh = blockIdx.y;
    const int b = bh >> 4, h = bh & 15, kvh = h >> 2;
    const int qt = gridDim.x - 1 - blockIdx.x;     // heavy tiles first
    const int qBase = qt * 64;

    const __half* qp = Q  + (size_t)b*T_*QCOLS_ + (size_t)h*HD_;
    const __half* kp = Kk + (size_t)b*T_*KCOLS_ + (size_t)kvh*HD_;
    const __half* vp = Vv + (size_t)b*T_*KCOLS_ + (size_t)kvh*HD_;

    auto load_kv = [&](int st, int kBase) {
        unsigned kb = qs_b + (1 + 2 * st) * AT_TILE;
        unsigned vb = kb + AT_TILE;
#pragma unroll
        for (int it = 0; it < 8; it++) {
            int ci = it * 128 + tid;
            int r = ci >> 4, c = ci & 15;
            cp_async16s(kb + r * AT_ROWB + c * 16,
                        kp + (size_t)(kBase + r) * KCOLS_ + c * 8);
            cp_async16s(vb + r * AT_ROWB + c * 16,
                        vp + (size_t)(kBase + r) * KCOLS_ + c * 8);
        }
        CP_COMMIT();
    };

    // ---- load Q tile via cp.async ----
#pragma unroll
    for (int it = 0; it < 8; it++) {
        int ci = it * 128 + tid;
        int r = ci >> 4, c = ci & 15;
        cp_async16s(qs_b + r * AT_ROWB + c * 16,
                    qp + (size_t)(qBase + r) * QCOLS_ + c * 8);
    }
    CP_COMMIT();
    load_kv(0, 0);

    CP_WAIT0();
    __syncthreads();

    // ---- hoist Q A-fragments (once per CTA) ----
    unsigned qa[8][4];
    {
        unsigned qrow = 16 * warp + ((lane >> 3) & 1) * 8 + (lane & 7);
        unsigned qbase = qs_b + qrow * AT_ROWB + (lane >> 4) * 16;
#pragma unroll
        for (int kc = 0; kc < 8; kc++)
            ldsm4(qa[kc][0], qa[kc][1], qa[kc][2], qa[kc][3], qbase + kc * 32);
    }

    const unsigned klo = ((lane >> 4) * 8 + (lane & 7)) * AT_ROWB + ((lane >> 3) & 1) * 16;
    const unsigned vlo = (((lane >> 3) & 1) * 8 + (lane & 7)) * AT_ROWB + (lane >> 4) * 16;

    float m0 = -INFINITY, m1 = -INFINITY, l0 = 0.f, l1 = 0.f;
    float o[16][4];
#pragma unroll
    for (int nf = 0; nf < 16; nf++)
#pragma unroll
        for (int q = 0; q < 4; q++) o[nf][q] = 0.f;

    const int r0g = qBase + 16 * warp + gid;
    const int r1g = r0g + 8;

    for (int jt = 0; jt <= qt; jt++) {
        const int kBase = jt * 64;

        if (jt > 0) { CP_WAIT0(); }
        __syncthreads();

        if (jt < qt) load_kv((jt + 1) & 1, kBase + 64);

        const unsigned kbl = qs_b + (1 + 2 * (jt & 1)) * AT_TILE + klo;
        const unsigned vbl = kbl + AT_TILE - klo + vlo;

        // ---- S = Q . K^T ----
        float s[8][4];
#pragma unroll
        for (int nf = 0; nf < 8; nf++)
#pragma unroll
            for (int q = 0; q < 4; q++) s[nf][q] = 0.f;

#pragma unroll
        for (int kc = 0; kc < 8; kc++) {
#pragma unroll
            for (int nfp = 0; nfp < 4; nfp++) {
                unsigned b0, b1, b2, b3;
                ldsm4(b0, b1, b2, b3, kbl + nfp * (16 * AT_ROWB) + kc * 32);
                unsigned bl[2] = { b0, b1 };
                unsigned bh2[2] = { b2, b3 };
                mma_f16(s[2*nfp],     qa[kc], bl);
                mma_f16(s[2*nfp + 1], qa[kc], bh2);
            }
        }

        // ---- softcap + causal mask ----
        const int cb = kBase + 2 * m4;
#pragma unroll
        for (int nf = 0; nf < 8; nf++) {
#pragma unroll
            for (int q = 0; q < 4; q++) {
                int col = cb + 8 * nf + (q & 1);
                int row = (q < 2) ? r0g : r1g;
                float val = CAP_ * tanh_fast(s[nf][q] * (1.0f / CAP_));
                s[nf][q] = (col > row) ? -INFINITY : val;
            }
        }

        // ---- online softmax ----
        float rmax0 = -INFINITY, rmax1 = -INFINITY;
#pragma unroll
        for (int nf = 0; nf < 8; nf++) {
            rmax0 = fmaxf(rmax0, fmaxf(s[nf][0], s[nf][1]));
            rmax1 = fmaxf(rmax1, fmaxf(s[nf][2], s[nf][3]));
        }
#pragma unroll
        for (int off = 1; off <= 2; off <<= 1) {
            rmax0 = fmaxf(rmax0, __shfl_xor_sync(0xffffffffu, rmax0, off));
            rmax1 = fmaxf(rmax1, __shfl_xor_sync(0xffffffffu, rmax1, off));
        }
        float mn0 = fmaxf(m0, rmax0), mn1 = fmaxf(m1, rmax1);
        float al0 = __expf(m0 - mn0), al1 = __expf(m1 - mn1);
        m0 = mn0; m1 = mn1;

        float rs0 = 0.f, rs1 = 0.f;
#pragma unroll
        for (int nf = 0; nf < 8; nf++) {
            float p0 = __expf(s[nf][0] - mn0);
            float p1 = __expf(s[nf][1] - mn0);
            float p2 = __expf(s[nf][2] - mn1);
            float p3 = __expf(s[nf][3] - mn1);
            rs0 += p0 + p1; rs1 += p2 + p3;
            s[nf][0] = p0; s[nf][1] = p1; s[nf][2] = p2; s[nf][3] = p3;
        }
#pragma unroll
        for (int off = 1; off <= 2; off <<= 1) {
            rs0 += __shfl_xor_sync(0xffffffffu, rs0, off);
            rs1 += __shfl_xor_sync(0xffffffffu, rs1, off);
        }
        l0 = l0 * al0 + rs0;
        l1 = l1 * al1 + rs1;
#pragma unroll
        for (int nf = 0; nf < 16; nf++) {
            o[nf][0] *= al0; o[nf][1] *= al0;
            o[nf][2] *= al1; o[nf][3] *= al1;
        }

        // ---- O += P . V ----
#pragma unroll
        for (int kc = 0; kc < 4; kc++) {
            unsigned pa[4];
            pa[0] = pack_h2(s[2*kc][0],     s[2*kc][1]);
            pa[1] = pack_h2(s[2*kc][2],     s[2*kc][3]);
            pa[2] = pack_h2(s[2*kc + 1][0], s[2*kc + 1][1]);
            pa[3] = pack_h2(s[2*kc + 1][2], s[2*kc + 1][3]);
#pragma unroll
            for (int nfp = 0; nfp < 8; nfp++) {
                unsigned b0, b1, b2, b3;
                ldsm4t(b0, b1, b2, b3, vbl + kc * (16 * AT_ROWB) + nfp * 32);
                unsigned bl[2] = { b0, b1 };
                unsigned bh2[2] = { b2, b3 };
                mma_f16(o[2*nfp],     pa, bl);
                mma_f16(o[2*nfp + 1], pa, bh2);
            }
        }
    }

    // ---- epilogue: /l, store half ----
    float inv0 = 1.0f / l0, inv1 = 1.0f / l1;
    __half* op0 = O + ((size_t)b*T_ + r0g) * QCOLS_ + (size_t)h*HD_;
    __half* op1 = O + ((size_t)b*T_ + r1g) * QCOLS_ + (size_t)h*HD_;
#pragma unroll
    for (int nf = 0; nf < 16; nf++) {
        int col = 8 * nf + 2 * m4;
        *(unsigned*)(op0 + col) = pack_h2(o[nf][0] * inv0, o[nf][1] * inv0);
        *(unsigned*)(op1 + col) = pack_h2(o[nf][2] * inv1, o[nf][3] * inv1);
    }
}

// ============================================================================
// launch
// ============================================================================
extern "C" void kernel_launch(void* const* d_in, const int* in_sizes, int n_in,
                              void* d_out, int out_size)
{
    const float* x  = (const float*)d_in[0];
    const float* wq = (const float*)d_in[1];
    const float* wk = (const float*)d_in[2];
    const float* wv = (const float*)d_in[3];
    const float* wo = (const float*)d_in[4];
    const float* qg = (const float*)d_in[5];
    const float* kg = (const float*)d_in[6];
    float* out = (float*)d_out;

    float *q, *k;
    __half *xh, *wqh, *wkh, *wvh, *woh, *qh, *kh, *vh, *oh;
    cudaGetSymbolAddress((void**)&q,   g_q);
    cudaGetSymbolAddress((void**)&k,   g_k);
    cudaGetSymbolAddress((void**)&xh,  g_xh);
    cudaGetSymbolAddress((void**)&wqh, g_wqh);
    cudaGetSymbolAddress((void**)&wkh, g_wkh);
    cudaGetSymbolAddress((void**)&wvh, g_wvh);
    cudaGetSymbolAddress((void**)&woh, g_woh);
    cudaGetSymbolAddress((void**)&qh,  g_qh);
    cudaGetSymbolAddress((void**)&kh,  g_kh);
    cudaGetSymbolAddress((void**)&vh,  g_vh);
    cudaGetSymbolAddress((void**)&oh,  g_oh);

    static bool attr_set = false;
    if (!attr_set) {
        cudaFuncSetAttribute(gemm_h<false>, cudaFuncAttributeMaxDynamicSharedMemorySize, GEMMH_SMEM);
        cudaFuncSetAttribute(gemm_h<true>,  cudaFuncAttributeMaxDynamicSharedMemorySize, GEMMH_SMEM);
        cudaFuncSetAttribute(attn_f16, cudaFuncAttributeMaxDynamicSharedMemorySize, ATTN_SMEM);
        attr_set = true;
    }

    // one-shot f32 -> f16 operand conversion
    cvt_h<<<(BT_*D_/4 + 255)/256, 256>>>(x,  xh,  BT_*D_/4);
    cvt_h<<<(QCOLS_*D_/4 + 255)/256, 256>>>(wq, wqh, QCOLS_*D_/4);
    cvt_h<<<(KCOLS_*D_/4 + 255)/256, 256>>>(wk, wkh, KCOLS_*D_/4);
    cvt_h<<<(KCOLS_*D_/4 + 255)/256, 256>>>(wv, wvh, KCOLS_*D_/4);
    cvt_h<<<(D_*QCOLS_/4 + 255)/256, 256>>>(wo, woh, D_*QCOLS_/4);

    // projections (fp16 ldmatrix GEMM, 128x256 tiles): q,k -> f32, v -> half
    gemm_h<false><<<dim3(QCOLS_/256, BT_/128), 256, GEMMH_SMEM>>>(xh, wqh, q,  BT_, QCOLS_, D_);
    gemm_h<false><<<dim3(KCOLS_/256, BT_/128), 256, GEMMH_SMEM>>>(xh, wkh, k,  BT_, KCOLS_, D_);
    gemm_h<true ><<<dim3(KCOLS_/256, BT_/128), 256, GEMMH_SMEM>>>(xh, wvh, vh, BT_, KCOLS_, D_);

    // QK-norm: f32 in, half out (scale folded into q)
    rmsnorm_cvt<<<(BT_*H_)/8, 256>>>(q, qh, qg, BT_*H_, SCALE_);
    rmsnorm_cvt<<<(BT_*KVH_)/8, 256>>>(k, kh, kg, BT_*KVH_, 1.0f);

    // attention (fp16 mma + ldmatrix, double-buffered K/V)
    attn_f16<<<dim3(T_/64, B_*H_), 128, ATTN_SMEM>>>(qh, kh, vh, oh);

    // output projection (half in, f32 out)
    gemm_h<false><<<dim3(D_/256, BT_/128), 256, GEMMH_SMEM>>>(oh, woh, out, BT_, D_, D_);
}

// round 17
// speedup vs baseline: 1.0948x; 1.0948x over previous
#include <cuda_runtime.h>
#include <cuda_fp16.h>
#include <math.h>
#include <stdint.h>

// ---- problem constants ----
#define D_   2048
#define H_   16
#define KVH_ 4
#define HD_  128
#define B_   2
#define T_   2048
#define BT_  (B_*T_)          // 4096
#define QCOLS_ (H_*HD_)       // 2048
#define KCOLS_ (KVH_*HD_)     // 512
#define CAP_ 50.0f
#define SCALE_ 0.08838834764831845f  // 128^-0.5

// ---- scratch (static device arrays; no allocations allowed) ----
static __device__ float  g_q[BT_*QCOLS_];      // q proj (f32, pre-norm)
static __device__ float  g_k[BT_*KCOLS_];      // k proj (f32, pre-norm)
static __device__ __half g_xh[BT_*D_];         // half copies of GEMM operands
static __device__ __half g_wqh[QCOLS_*D_];
static __device__ __half g_wkh[KCOLS_*D_];
static __device__ __half g_wvh[KCOLS_*D_];
static __device__ __half g_woh[D_*QCOLS_];
static __device__ __half g_qh[BT_*QCOLS_];     // post-norm half q
static __device__ __half g_kh[BT_*KCOLS_];     // post-norm half k
static __device__ __half g_vh[BT_*KCOLS_];     // v (half, direct from GEMM)
static __device__ __half g_oh[BT_*QCOLS_];     // attention out (half)

// ============================================================================
// helpers
// ============================================================================
__device__ __forceinline__ unsigned pack_h2(float lo, float hi) {
    unsigned u;
    asm("cvt.rn.f16x2.f32 %0, %1, %2;" : "=r"(u) : "f"(hi), "f"(lo));
    return u;
}

__device__ __forceinline__ void mma_f16(float* c, const unsigned* a, const unsigned* b) {
    asm volatile(
        "mma.sync.aligned.m16n8k16.row.col.f32.f16.f16.f32 "
        "{%0,%1,%2,%3}, {%4,%5,%6,%7}, {%8,%9}, {%0,%1,%2,%3};"
        : "+f"(c[0]), "+f"(c[1]), "+f"(c[2]), "+f"(c[3])
        : "r"(a[0]), "r"(a[1]), "r"(a[2]), "r"(a[3]), "r"(b[0]), "r"(b[1]));
}

__device__ __forceinline__ void ldsm4(unsigned& r0, unsigned& r1, unsigned& r2, unsigned& r3,
                                      unsigned addr) {
    asm volatile("ldmatrix.sync.aligned.m8n8.x4.shared.b16 {%0,%1,%2,%3}, [%4];"
        : "=r"(r0), "=r"(r1), "=r"(r2), "=r"(r3) : "r"(addr));
}

__device__ __forceinline__ void ldsm4t(unsigned& r0, unsigned& r1, unsigned& r2, unsigned& r3,
                                       unsigned addr) {
    asm volatile("ldmatrix.sync.aligned.m8n8.x4.trans.shared.b16 {%0,%1,%2,%3}, [%4];"
        : "=r"(r0), "=r"(r1), "=r"(r2), "=r"(r3) : "r"(addr));
}

__device__ __forceinline__ float tanh_fast(float x) {
    float r;
    asm("tanh.approx.f32 %0, %1;" : "=f"(r) : "f"(x));
    return r;
}

__device__ __forceinline__ void cp_async16s(unsigned saddr, const void* gsrc) {
    asm volatile("cp.async.cg.shared.global [%0], [%1], 16;" :: "r"(saddr), "l"(gsrc));
}
#define CP_COMMIT() asm volatile("cp.async.commit_group;")
#define CP_WAIT0()  asm volatile("cp.async.wait_group 0;")
#define CP_WAIT1()  asm volatile("cp.async.wait_group 1;")

// ============================================================================
// f32 -> f16 elementwise (4 floats per thread)
// ============================================================================
__global__ __launch_bounds__(256) void cvt_h(
    const float* __restrict__ in, __half* __restrict__ out, int n4)
{
    int i = blockIdx.x * 256 + threadIdx.x;
    if (i >= n4) return;
    float4 v = ((const float4*)in)[i];
    uint2 u;
    u.x = pack_h2(v.x, v.y);
    u.y = pack_h2(v.z, v.w);
    ((uint2*)out)[i] = u;
}

// ============================================================================
// fp16 GEMM v5: R15 structure (128x128x64 tiles, 256 thr, 8 warps 4x2,
// ldmatrix, 144B row pad) with a 3-STAGE cp.async ring + wait_group 1:
// each load gets ~2 compute-stages of slack. Single barrier per iteration
// (compute(t-1) finishes before sync(t), so loading (t+2)%3 after it is safe).
// 110.6KB smem -> 2 CTAs/SM preserved.
// ============================================================================
#define GBK 64
#define GROWB 144
#define GSTG (128*GROWB*2)               // A+B per stage = 36864 B
#define GEMMH_SMEM (3*GSTG)              // 110592 B

template<bool HOUT>
__global__ __launch_bounds__(256) void gemm_h(
    const __half* __restrict__ A, const __half* __restrict__ Bw,
    void* __restrict__ Cv, int M, int N, int K)
{
    extern __shared__ char gsm[];
    const unsigned sb = (unsigned)__cvta_generic_to_shared(gsm);

    const int tid  = threadIdx.x;
    const int lane = tid & 31;
    const int warp = tid >> 5;
    const int gid  = lane >> 2, m4 = lane & 3;
    const int wm = (warp & 3) * 32;
    const int wn = (warp >> 2) * 64;
    const int rowBase = blockIdx.y * 128;
    const int colBase = blockIdx.x * 128;

    float acc[2][8][4];
#pragma unroll
    for (int mi = 0; mi < 2; mi++)
#pragma unroll
        for (int ni = 0; ni < 8; ni++)
#pragma unroll
            for (int q = 0; q < 4; q++) acc[mi][ni][q] = 0.f;

    const int nt = K / GBK;

    auto load_stage = [&](int st, int k0) {
        unsigned base = sb + st * GSTG;
#pragma unroll
        for (int it = 0; it < 4; it++) {
            int ci = it * 256 + tid;
            int r = ci >> 3, c = ci & 7;
            cp_async16s(base + r * GROWB + c * 16,
                        A + (size_t)(rowBase + r) * K + k0 + c * 8);
            cp_async16s(base + 128 * GROWB + r * GROWB + c * 16,
                        Bw + (size_t)(colBase + r) * K + k0 + c * 8);
        }
        CP_COMMIT();
    };

    // prologue: stages 0, 1
    load_stage(0, 0);
    load_stage(1, GBK);

    const unsigned abo = (wm + ((lane >> 3) & 1) * 8 + (lane & 7)) * GROWB + (lane >> 4) * 16;
    const unsigned bbo = 128 * GROWB + (wn + (lane >> 4) * 8 + (lane & 7)) * GROWB
                       + ((lane >> 3) & 1) * 16;

    for (int t = 0; t < nt; t++) {
        const int st = t % 3;
        if (t == nt - 1) { CP_WAIT0(); } else { CP_WAIT1(); }
        __syncthreads();

        if (t + 2 < nt) load_stage((t + 2) % 3, (t + 2) * GBK);

        const unsigned ab = sb + st * GSTG + abo;
        const unsigned bb = sb + st * GSTG + bbo;
#pragma unroll
        for (int ks = 0; ks < 4; ks++) {
            unsigned a0[4], a1[4];
            ldsm4(a0[0], a0[1], a0[2], a0[3], ab + ks * 32);
            ldsm4(a1[0], a1[1], a1[2], a1[3], ab + 16 * GROWB + ks * 32);
#pragma unroll
            for (int nfp = 0; nfp < 4; nfp++) {
                unsigned b0, b1, b2, b3;
                ldsm4(b0, b1, b2, b3, bb + nfp * (16 * GROWB) + ks * 32);
                unsigned bl[2] = { b0, b1 };
                unsigned bh2[2] = { b2, b3 };
                mma_f16(acc[0][2*nfp],     a0, bl);
                mma_f16(acc[0][2*nfp + 1], a0, bh2);
                mma_f16(acc[1][2*nfp],     a1, bl);
                mma_f16(acc[1][2*nfp + 1], a1, bh2);
            }
        }
    }

    // ---- epilogue ----
#pragma unroll
    for (int mi = 0; mi < 2; mi++) {
        int r0 = rowBase + wm + 16 * mi + gid;
#pragma unroll
        for (int ni = 0; ni < 8; ni++) {
            int c0 = colBase + wn + ni * 8 + m4 * 2;
            if (HOUT) {
                __half* C = (__half*)Cv;
                *(unsigned*)(C + (size_t)r0       * N + c0) = pack_h2(acc[mi][ni][0], acc[mi][ni][1]);
                *(unsigned*)(C + (size_t)(r0 + 8) * N + c0) = pack_h2(acc[mi][ni][2], acc[mi][ni][3]);
            } else {
                float* C = (float*)Cv;
                *(float2*)(C + (size_t)r0       * N + c0) = make_float2(acc[mi][ni][0], acc[mi][ni][1]);
                *(float2*)(C + (size_t)(r0 + 8) * N + c0) = make_float2(acc[mi][ni][2], acc[mi][ni][3]);
            }
        }
    }
}

// ============================================================================
// RMSNorm: f32 in, half out. One warp per 128-elem row. Scale folded (q).
// ============================================================================
__global__ __launch_bounds__(256) void rmsnorm_cvt(
    const float* __restrict__ in, __half* __restrict__ out,
    const float* __restrict__ gamma, int nrows, float scale)
{
    int row  = blockIdx.x * 8 + (threadIdx.x >> 5);
    int lane = threadIdx.x & 31;
    if (row >= nrows) return;
    float4 v = ((const float4*)in)[(size_t)row * 32 + lane];
    float ss = v.x*v.x + v.y*v.y + v.z*v.z + v.w*v.w;
#pragma unroll
    for (int off = 16; off > 0; off >>= 1)
        ss += __shfl_xor_sync(0xffffffffu, ss, off);
    float r = rsqrtf(ss * (1.0f/128.0f) + 1e-6f) * scale;
    float4 g = ((const float4*)gamma)[lane];
    uint2 u;
    u.x = pack_h2(v.x * r * g.x, v.y * r * g.y);
    u.y = pack_h2(v.z * r * g.z, v.w * r * g.w);
    ((uint2*)(out + (size_t)row * 128))[lane] = u;
}

// ============================================================================
// fp16 flash attention (R15, unchanged): double-buffered K/V, ldmatrix,
// half in / half out.
// ============================================================================
#define AT_LDH 136
#define AT_ROWB (AT_LDH*2)               // 272 B per row
#define AT_TILE (64*AT_ROWB)             // 17408 B per tile
#define ATTN_SMEM (5*AT_TILE)            // 87040 B

__global__ __launch_bounds__(128) void attn_f16(
    const __half* __restrict__ Q, const __half* __restrict__ Kk,
    const __half* __restrict__ Vv, __half* __restrict__ O)
{
    extern __shared__ char smc[];
    const unsigned qs_b = (unsigned)__cvta_generic_to_shared(smc);

    const int tid  = threadIdx.x;
    const int lane = tid & 31;
    const int warp = tid >> 5;
    const int gid  = lane >> 2;
    const int m4   = lane & 3;

    const int bh = blockIdx.y;
    const int b = bh >> 4, h = bh & 15, kvh = h >> 2;
    const int qt = gridDim.x - 1 - blockIdx.x;     // heavy tiles first
    const int qBase = qt * 64;

    const __half* qp = Q  + (size_t)b*T_*QCOLS_ + (size_t)h*HD_;
    const __half* kp = Kk + (size_t)b*T_*KCOLS_ + (size_t)kvh*HD_;
    const __half* vp = Vv + (size_t)b*T_*KCOLS_ + (size_t)kvh*HD_;

    auto load_kv = [&](int st, int kBase) {
        unsigned kb = qs_b + (1 + 2 * st) * AT_TILE;
        unsigned vb = kb + AT_TILE;
#pragma unroll
        for (int it = 0; it < 8; it++) {
            int ci = it * 128 + tid;
            int r = ci >> 4, c = ci & 15;
            cp_async16s(kb + r * AT_ROWB + c * 16,
                        kp + (size_t)(kBase + r) * KCOLS_ + c * 8);
            cp_async16s(vb + r * AT_ROWB + c * 16,
                        vp + (size_t)(kBase + r) * KCOLS_ + c * 8);
        }
        CP_COMMIT();
    };

    // ---- load Q tile via cp.async ----
#pragma unroll
    for (int it = 0; it < 8; it++) {
        int ci = it * 128 + tid;
        int r = ci >> 4, c = ci & 15;
        cp_async16s(qs_b + r * AT_ROWB + c * 16,
                    qp + (size_t)(qBase + r) * QCOLS_ + c * 8);
    }
    CP_COMMIT();
    load_kv(0, 0);

    CP_WAIT0();
    __syncthreads();

    // ---- hoist Q A-fragments (once per CTA) ----
    unsigned qa[8][4];
    {
        unsigned qrow = 16 * warp + ((lane >> 3) & 1) * 8 + (lane & 7);
        unsigned qbase = qs_b + qrow * AT_ROWB + (lane >> 4) * 16;
#pragma unroll
        for (int kc = 0; kc < 8; kc++)
            ldsm4(qa[kc][0], qa[kc][1], qa[kc][2], qa[kc][3], qbase + kc * 32);
    }

    const unsigned klo = ((lane >> 4) * 8 + (lane & 7)) * AT_ROWB + ((lane >> 3) & 1) * 16;
    const unsigned vlo = (((lane >> 3) & 1) * 8 + (lane & 7)) * AT_ROWB + (lane >> 4) * 16;

    float m0 = -INFINITY, m1 = -INFINITY, l0 = 0.f, l1 = 0.f;
    float o[16][4];
#pragma unroll
    for (int nf = 0; nf < 16; nf++)
#pragma unroll
        for (int q = 0; q < 4; q++) o[nf][q] = 0.f;

    const int r0g = qBase + 16 * warp + gid;
    const int r1g = r0g + 8;

    for (int jt = 0; jt <= qt; jt++) {
        const int kBase = jt * 64;

        if (jt > 0) { CP_WAIT0(); }
        __syncthreads();

        if (jt < qt) load_kv((jt + 1) & 1, kBase + 64);

        const unsigned kbl = qs_b + (1 + 2 * (jt & 1)) * AT_TILE + klo;
        const unsigned vbl = kbl + AT_TILE - klo + vlo;

        // ---- S = Q . K^T ----
        float s[8][4];
#pragma unroll
        for (int nf = 0; nf < 8; nf++)
#pragma unroll
            for (int q = 0; q < 4; q++) s[nf][q] = 0.f;

#pragma unroll
        for (int kc = 0; kc < 8; kc++) {
#pragma unroll
            for (int nfp = 0; nfp < 4; nfp++) {
                unsigned b0, b1, b2, b3;
                ldsm4(b0, b1, b2, b3, kbl + nfp * (16 * AT_ROWB) + kc * 32);
                unsigned bl[2] = { b0, b1 };
                unsigned bh2[2] = { b2, b3 };
                mma_f16(s[2*nfp],     qa[kc], bl);
                mma_f16(s[2*nfp + 1], qa[kc], bh2);
            }
        }

        // ---- softcap + causal mask ----
        const int cb = kBase + 2 * m4;
#pragma unroll
        for (int nf = 0; nf < 8; nf++) {
#pragma unroll
            for (int q = 0; q < 4; q++) {
                int col = cb + 8 * nf + (q & 1);
                int row = (q < 2) ? r0g : r1g;
                float val = CAP_ * tanh_fast(s[nf][q] * (1.0f / CAP_));
                s[nf][q] = (col > row) ? -INFINITY : val;
            }
        }

        // ---- online softmax ----
        float rmax0 = -INFINITY, rmax1 = -INFINITY;
#pragma unroll
        for (int nf = 0; nf < 8; nf++) {
            rmax0 = fmaxf(rmax0, fmaxf(s[nf][0], s[nf][1]));
            rmax1 = fmaxf(rmax1, fmaxf(s[nf][2], s[nf][3]));
        }
#pragma unroll
        for (int off = 1; off <= 2; off <<= 1) {
            rmax0 = fmaxf(rmax0, __shfl_xor_sync(0xffffffffu, rmax0, off));
            rmax1 = fmaxf(rmax1, __shfl_xor_sync(0xffffffffu, rmax1, off));
        }
        float mn0 = fmaxf(m0, rmax0), mn1 = fmaxf(m1, rmax1);
        float al0 = __expf(m0 - mn0), al1 = __expf(m1 - mn1);
        m0 = mn0; m1 = mn1;

        float rs0 = 0.f, rs1 = 0.f;
#pragma unroll
        for (int nf = 0; nf < 8; nf++) {
            float p0 = __expf(s[nf][0] - mn0);
            float p1 = __expf(s[nf][1] - mn0);
            float p2 = __expf(s[nf][2] - mn1);
            float p3 = __expf(s[nf][3] - mn1);
            rs0 += p0 + p1; rs1 += p2 + p3;
            s[nf][0] = p0; s[nf][1] = p1; s[nf][2] = p2; s[nf][3] = p3;
        }
#pragma unroll
        for (int off = 1; off <= 2; off <<= 1) {
            rs0 += __shfl_xor_sync(0xffffffffu, rs0, off);
            rs1 += __shfl_xor_sync(0xffffffffu, rs1, off);
        }
        l0 = l0 * al0 + rs0;
        l1 = l1 * al1 + rs1;
#pragma unroll
        for (int nf = 0; nf < 16; nf++) {
            o[nf][0] *= al0; o[nf][1] *= al0;
            o[nf][2] *= al1; o[nf][3] *= al1;
        }

        // ---- O += P . V ----
#pragma unroll
        for (int kc = 0; kc < 4; kc++) {
            unsigned pa[4];
            pa[0] = pack_h2(s[2*kc][0],     s[2*kc][1]);
            pa[1] = pack_h2(s[2*kc][2],     s[2*kc][3]);
            pa[2] = pack_h2(s[2*kc + 1][0], s[2*kc + 1][1]);
            pa[3] = pack_h2(s[2*kc + 1][2], s[2*kc + 1][3]);
#pragma unroll
            for (int nfp = 0; nfp < 8; nfp++) {
                unsigned b0, b1, b2, b3;
                ldsm4t(b0, b1, b2, b3, vbl + kc * (16 * AT_ROWB) + nfp * 32);
                unsigned bl[2] = { b0, b1 };
                unsigned bh2[2] = { b2, b3 };
                mma_f16(o[2*nfp],     pa, bl);
                mma_f16(o[2*nfp + 1], pa, bh2);
            }
        }
    }

    // ---- epilogue: /l, store half ----
    float inv0 = 1.0f / l0, inv1 = 1.0f / l1;
    __half* op0 = O + ((size_t)b*T_ + r0g) * QCOLS_ + (size_t)h*HD_;
    __half* op1 = O + ((size_t)b*T_ + r1g) * QCOLS_ + (size_t)h*HD_;
#pragma unroll
    for (int nf = 0; nf < 16; nf++) {
        int col = 8 * nf + 2 * m4;
        *(unsigned*)(op0 + col) = pack_h2(o[nf][0] * inv0, o[nf][1] * inv0);
        *(unsigned*)(op1 + col) = pack_h2(o[nf][2] * inv1, o[nf][3] * inv1);
    }
}

// ============================================================================
// launch
// ============================================================================
extern "C" void kernel_launch(void* const* d_in, const int* in_sizes, int n_in,
                              void* d_out, int out_size)
{
    const float* x  = (const float*)d_in[0];
    const float* wq = (const float*)d_in[1];
    const float* wk = (const float*)d_in[2];
    const float* wv = (const float*)d_in[3];
    const float* wo = (const float*)d_in[4];
    const float* qg = (const float*)d_in[5];
    const float* kg = (const float*)d_in[6];
    float* out = (float*)d_out;

    float *q, *k;
    __half *xh, *wqh, *wkh, *wvh, *woh, *qh, *kh, *vh, *oh;
    cudaGetSymbolAddress((void**)&q,   g_q);
    cudaGetSymbolAddress((void**)&k,   g_k);
    cudaGetSymbolAddress((void**)&xh,  g_xh);
    cudaGetSymbolAddress((void**)&wqh, g_wqh);
    cudaGetSymbolAddress((void**)&wkh, g_wkh);
    cudaGetSymbolAddress((void**)&wvh, g_wvh);
    cudaGetSymbolAddress((void**)&woh, g_woh);
    cudaGetSymbolAddress((void**)&qh,  g_qh);
    cudaGetSymbolAddress((void**)&kh,  g_kh);
    cudaGetSymbolAddress((void**)&vh,  g_vh);
    cudaGetSymbolAddress((void**)&oh,  g_oh);

    static bool attr_set = false;
    if (!attr_set) {
        cudaFuncSetAttribute(gemm_h<false>, cudaFuncAttributeMaxDynamicSharedMemorySize, GEMMH_SMEM);
        cudaFuncSetAttribute(gemm_h<true>,  cudaFuncAttributeMaxDynamicSharedMemorySize, GEMMH_SMEM);
        cudaFuncSetAttribute(attn_f16, cudaFuncAttributeMaxDynamicSharedMemorySize, ATTN_SMEM);
        attr_set = true;
    }

    // one-shot f32 -> f16 operand conversion
    cvt_h<<<(BT_*D_/4 + 255)/256, 256>>>(x,  xh,  BT_*D_/4);
    cvt_h<<<(QCOLS_*D_/4 + 255)/256, 256>>>(wq, wqh, QCOLS_*D_/4);
    cvt_h<<<(KCOLS_*D_/4 + 255)/256, 256>>>(wk, wkh, KCOLS_*D_/4);
    cvt_h<<<(KCOLS_*D_/4 + 255)/256, 256>>>(wv, wvh, KCOLS_*D_/4);
    cvt_h<<<(D_*QCOLS_/4 + 255)/256, 256>>>(wo, woh, D_*QCOLS_/4);

    // projections (fp16 ldmatrix GEMM, 128x128, 3-stage): q,k -> f32, v -> half
    gemm_h<false><<<dim3(QCOLS_/128, BT_/128), 256, GEMMH_SMEM>>>(xh, wqh, q,  BT_, QCOLS_, D_);
    gemm_h<false><<<dim3(KCOLS_/128, BT_/128), 256, GEMMH_SMEM>>>(xh, wkh, k,  BT_, KCOLS_, D_);
    gemm_h<true ><<<dim3(KCOLS_/128, BT_/128), 256, GEMMH_SMEM>>>(xh, wvh, vh, BT_, KCOLS_, D_);

    // QK-norm: f32 in, half out (scale folded into q)
    rmsnorm_cvt<<<(BT_*H_)/8, 256>>>(q, qh, qg, BT_*H_, SCALE_);
    rmsnorm_cvt<<<(BT_*KVH_)/8, 256>>>(k, kh, kg, BT_*KVH_, 1.0f);

    // attention (fp16 mma + ldmatrix, double-buffered K/V)
    attn_f16<<<dim3(T_/64, B_*H_), 128, ATTN_SMEM>>>(qh, kh, vh, oh);

    // output projection (half in, f32 out)
    gemm_h<false><<<dim3(D_/128, BT_/128), 256, GEMMH_SMEM>>>(oh, woh, out, BT_, D_, D_);
}